// round 10
// baseline (speedup 1.0000x reference)
#include <cuda_runtime.h>
#include <cuda_fp16.h>
#include <mma.h>

using namespace nvcuda;

#define N_ATOMS 20000
#define N_PAIRS 320000
#define FDIM 128
#define CAP 64            // slots per atom (mean 16, 8-sigma margin)

// ---------------- scratch (device globals; no allocation allowed) ----------
__device__ __half g_Ah[N_ATOMS * FDIM];          // fp16 A        (5.12 MB)
__device__ __half g_Bh[N_ATOMS * FDIM];          // B = A @ W^T   (5.12 MB)
__device__ __half g_Wh[FDIM * FDIM];             // fp16 W        (32 KB)
__device__ int    g_cursor[N_ATOMS];
__device__ float4 g_P[N_ATOMS * CAP];            // payload buckets (20 MB)

// ---------------------------------------------------------------------------
// Kernel 0: convert W to fp16 (one-shot, 16K elems)
// ---------------------------------------------------------------------------
__global__ __launch_bounds__(256) void convW_kernel(const float* __restrict__ W)
{
    int i = blockIdx.x * blockDim.x + threadIdx.x;   // float4 index
    if (i < FDIM * FDIM / 4) {
        float4 v = ((const float4*)W)[i];
        __half2 h0 = __floats2half2_rn(v.x, v.y);
        __half2 h1 = __floats2half2_rn(v.z, v.w);
        uint2 o;
        o.x = *reinterpret_cast<unsigned*>(&h0);
        o.y = *reinterpret_cast<unsigned*>(&h1);
        ((uint2*)g_Wh)[i] = o;
    }
}

// ---------------------------------------------------------------------------
// Kernel 1 (fused): convert A->fp16 (write g_Ah) AND B = A @ W^T via wmma.
// 256 threads / 128 A-rows per block. smem = 32KB A-tile, reused as fp32
// staging buffer after the MMAs. W fragments load directly from global
// (g_Wh is 32KB, L1-resident, broadcast across blocks).
// ---------------------------------------------------------------------------
__global__ __launch_bounds__(256) void gemm_wmma_kernel(const float* __restrict__ A)
{
    __shared__ __align__(16) __half As[128 * FDIM];   // 32 KB (reused as stage)

    const int tid  = threadIdx.x;
    const int w    = tid >> 5;
    const int lane = tid & 31;
    const int row0 = blockIdx.x * 128;

    // --- load A tile fp32 -> fp16 smem, and write g_Ah (fused convA) ---
#pragma unroll
    for (int i = tid; i < 128 * FDIM / 4; i += 256) {
        int r = i >> 5;                  // row in tile
        int grow = row0 + r;
        uint2 o;
        if (grow < N_ATOMS) {
            float4 v = ((const float4*)A)[(size_t)grow * (FDIM / 4) + (i & 31)];
            __half2 h0 = __floats2half2_rn(v.x, v.y);
            __half2 h1 = __floats2half2_rn(v.z, v.w);
            o.x = *reinterpret_cast<unsigned*>(&h0);
            o.y = *reinterpret_cast<unsigned*>(&h1);
            ((uint2*)g_Ah)[(size_t)grow * (FDIM / 4) + (i & 31)] = o;
        } else {
            o.x = 0u; o.y = 0u;
        }
        ((uint2*)As)[i] = o;
    }
    __syncthreads();

    // --- wmma: each warp does 16 rows x 128 cols, B frags from global ---
    wmma::fragment<wmma::accumulator, 16, 16, 16, float> c[8];
#pragma unroll
    for (int n = 0; n < 8; n++) wmma::fill_fragment(c[n], 0.0f);

    const int m0 = w * 16;
#pragma unroll
    for (int k0 = 0; k0 < 8; k0++) {
        wmma::fragment<wmma::matrix_a, 16, 16, 16, __half, wmma::row_major> a;
        wmma::load_matrix_sync(a, As + m0 * FDIM + k0 * 16, FDIM);
#pragma unroll
        for (int n = 0; n < 8; n++) {
            wmma::fragment<wmma::matrix_b, 16, 16, 16, __half, wmma::col_major> bfr;
            // B(k,n) = Wh[n*128 + k]  (W row-major [g][f] == col-major K x N)
            wmma::load_matrix_sync(bfr, g_Wh + (n * 16) * FDIM + k0 * 16, FDIM);
            wmma::mma_sync(c[n], a, bfr, c[n]);
        }
    }
    __syncthreads();   // all MMAs done; As is now free for staging

    float* stage = (float*)As;   // 4 warps x 16x128 fp32 = 32 KB per wave

    // --- stage fp32 -> convert fp16 -> g_Bh, two waves of 4 warps ---
#pragma unroll
    for (int wave = 0; wave < 2; wave++) {
        if ((w >> 2) == wave) {
            float* sp = stage + (w & 3) * 16 * FDIM;
#pragma unroll
            for (int n = 0; n < 8; n++)
                wmma::store_matrix_sync(sp + n * 16, c[n], FDIM, wmma::mem_row_major);
#pragma unroll
            for (int i = lane; i < 16 * 32; i += 32) {
                int r = i >> 5, c4 = i & 31;
                int grow = row0 + m0 + r;
                if (grow < N_ATOMS) {
                    float4 v = *(const float4*)(sp + r * FDIM + c4 * 4);
                    __half2 h0 = __floats2half2_rn(v.x, v.y);
                    __half2 h1 = __floats2half2_rn(v.z, v.w);
                    uint2 o;
                    o.x = *reinterpret_cast<unsigned*>(&h0);
                    o.y = *reinterpret_cast<unsigned*>(&h1);
                    ((uint2*)g_Bh)[(size_t)grow * (FDIM / 4) + c4] = o;
                }
            }
        }
        __syncthreads();
    }
}

// ---------------------------------------------------------------------------
// Kernel 2: scatter payload into fixed-stride buckets (4 pairs/thread).
// Payload float4 = { j (bits), f (fp32), (ux,uy) fp16x2, (uz,0) fp16x2 }
// ---------------------------------------------------------------------------
__global__ __launch_bounds__(256) void scatter_kernel(
    const int* __restrict__ idx_i, const int* __restrict__ idx_j,
    const float* __restrict__ fcut, const float* __restrict__ r_ij)
{
    int t = blockIdx.x * blockDim.x + threadIdx.x;
    if (t >= N_PAIRS / 4) return;

    int4   ii = ((const int4*)idx_i)[t];
    int4   jj = ((const int4*)idx_j)[t];
    float4 ff = ((const float4*)fcut)[t];
    float4 r0 = ((const float4*)r_ij)[3 * t + 0];
    float4 r1 = ((const float4*)r_ij)[3 * t + 1];
    float4 r2 = ((const float4*)r_ij)[3 * t + 2];

    float rx[4] = {r0.x, r0.w, r1.z, r2.y};
    float ry[4] = {r0.y, r1.x, r1.w, r2.z};
    float rz[4] = {r0.z, r1.y, r2.x, r2.w};
    int   iv[4] = {ii.x, ii.y, ii.z, ii.w};
    int   jv[4] = {jj.x, jj.y, jj.z, jj.w};
    float fv[4] = {ff.x, ff.y, ff.z, ff.w};

#pragma unroll
    for (int q = 0; q < 4; q++) {
        float inv = rsqrtf(rx[q] * rx[q] + ry[q] * ry[q] + rz[q] * rz[q]);
        __half2 uxy = __floats2half2_rn(rx[q] * inv, ry[q] * inv);
        __half2 uzp = __floats2half2_rn(rz[q] * inv, 0.0f);
        int pos = atomicAdd(&g_cursor[iv[q]], 1);
        if (pos < CAP) {
            float4 pl;
            pl.x = __int_as_float(jv[q]);
            pl.y = fv[q];
            pl.z = *reinterpret_cast<float*>(&uxy);
            pl.w = *reinterpret_cast<float*>(&uzp);
            g_P[(size_t)iv[q] * CAP + pos] = pl;
        }
    }
}

// ---------------------------------------------------------------------------
// Kernel 3: one warp per atom; fp16 gathers; unroll x4 for MLP.
// ---------------------------------------------------------------------------
__device__ __forceinline__ void acc_pair(
    const float4& pl, int col,
    float rad[4], float sx[4], float sy[4], float sz[4])
{
    int   j = __float_as_int(pl.x);
    float f = pl.y;
    __half2 uxy = *reinterpret_cast<const __half2*>(&pl.z);
    __half2 uzp = *reinterpret_cast<const __half2*>(&pl.w);
    float2 uf = __half22float2(uxy);
    float ux = uf.x, uy = uf.y, uz = __low2float(uzp);

    uint2 ua = *(const uint2*)(g_Ah + (size_t)j * FDIM + col);
    uint2 ub = *(const uint2*)(g_Bh + (size_t)j * FDIM + col);
    float2 af0 = __half22float2(*reinterpret_cast<__half2*>(&ua.x));
    float2 af1 = __half22float2(*reinterpret_cast<__half2*>(&ua.y));
    float2 bf0 = __half22float2(*reinterpret_cast<__half2*>(&ub.x));
    float2 bf1 = __half22float2(*reinterpret_cast<__half2*>(&ub.y));
    float av[4] = {af0.x, af0.y, af1.x, af1.y};
    float bv[4] = {bf0.x, bf0.y, bf1.x, bf1.y};
#pragma unroll
    for (int k = 0; k < 4; k++) {
        rad[k] += f * av[k];
        float tb = f * bv[k];
        sx[k] += ux * tb;
        sy[k] += uy * tb;
        sz[k] += uz * tb;
    }
}

__global__ __launch_bounds__(256) void phase2_kernel(
    const float* __restrict__ bvec, float* __restrict__ out)
{
    int atom = (blockIdx.x * blockDim.x + threadIdx.x) >> 5;
    int lane = threadIdx.x & 31;
    if (atom >= N_ATOMS) return;

    const int ntrue = g_cursor[atom];
    const int n     = (ntrue < CAP) ? ntrue : CAP;
    const float4* __restrict__ seg = g_P + (size_t)atom * CAP;
    const int col = lane * 4;

    float rad[4] = {0.f, 0.f, 0.f, 0.f};
    float sx[4]  = {0.f, 0.f, 0.f, 0.f};
    float sy[4]  = {0.f, 0.f, 0.f, 0.f};
    float sz[4]  = {0.f, 0.f, 0.f, 0.f};

    int t = 0;
    for (; t + 4 <= n; t += 4) {
        float4 p0 = seg[t + 0];
        float4 p1 = seg[t + 1];
        float4 p2 = seg[t + 2];
        float4 p3 = seg[t + 3];
        acc_pair(p0, col, rad, sx, sy, sz);
        acc_pair(p1, col, rad, sx, sy, sz);
        acc_pair(p2, col, rad, sx, sy, sz);
        acc_pair(p3, col, rad, sx, sy, sz);
    }
    for (; t < n; t++) {
        float4 p0 = seg[t];
        acc_pair(p0, col, rad, sx, sy, sz);
    }

    float4 bq = *(const float4*)(bvec + col);
    float bvv[4] = {bq.x, bq.y, bq.z, bq.w};
    float fn = (float)ntrue;
    float nrm[4];
#pragma unroll
    for (int k = 0; k < 4; k++) {
        float vx = sx[k] + fn * bvv[k];
        float vy = sy[k] + fn * bvv[k];
        float vz = sz[k] + fn * bvv[k];
        nrm[k] = sqrtf(vx * vx + vy * vy + vz * vz + 1e-12f);
    }

    float4 o0 = {nrm[0], nrm[1], nrm[2], nrm[3]};
    float4 o1 = {rad[0], rad[1], rad[2], rad[3]};
    *(float4*)(out + (size_t)atom * (2 * FDIM) + col)        = o0;
    *(float4*)(out + (size_t)atom * (2 * FDIM) + FDIM + col) = o1;
}

// ---------------------------------------------------------------------------
extern "C" void kernel_launch(void* const* d_in, const int* in_sizes, int n_in,
                              void* d_out, int out_size)
{
    const float* A    = (const float*)d_in[0];   // [20000,128]
    const int*   pl   = (const int*)  d_in[1];   // [2,320000]
    const float* fcut = (const float*)d_in[2];   // [320000,1]
    const float* rij  = (const float*)d_in[3];   // [320000,3]
    const float* W    = (const float*)d_in[4];   // [128,128]
    const float* b    = (const float*)d_in[5];   // [128]
    const int* idx_i = pl;
    const int* idx_j = pl + N_PAIRS;
    float* out = (float*)d_out;

    void* p_cursor;
    cudaGetSymbolAddress(&p_cursor, g_cursor);
    cudaMemsetAsync(p_cursor, 0, N_ATOMS * sizeof(int));

    convW_kernel<<<(FDIM * FDIM / 4 + 255) / 256, 256>>>(W);
    gemm_wmma_kernel<<<(N_ATOMS + 127) / 128, 256>>>(A);
    scatter_kernel<<<(N_PAIRS / 4 + 255) / 256, 256>>>(idx_i, idx_j, fcut, rij);
    phase2_kernel<<<(N_ATOMS * 32 + 255) / 256, 256>>>(b, out);
}

// round 11
// speedup vs baseline: 1.1612x; 1.1612x over previous
#include <cuda_runtime.h>
#include <cuda_fp16.h>
#include <mma.h>

using namespace nvcuda;

#define N_ATOMS 20000
#define N_PAIRS 320000
#define FDIM 128
#define CAP 64            // slots per atom (mean 16, 8-sigma margin)

// ---------------- scratch (device globals; no allocation allowed) ----------
// Interleaved table: per atom j, 256 halves: group c (0..31) holds
// { A[j][4c..4c+3], B[j][4c..4c+3] } so lane c reads ONE uint4.
__device__ __align__(16) __half g_ABh[N_ATOMS * 2 * FDIM];   // 10.24 MB
__device__ int    g_cursor[N_ATOMS];
__device__ float4 g_P[N_ATOMS * CAP];                        // payload buckets

// ---------------------------------------------------------------------------
// Kernel 1 (fused): B = A @ W^T via wmma; writes interleaved fp16 A|B table.
// 256 threads, 128 A-rows/block. Dynamic smem 64KB: Wh 32KB | As 32KB.
// After MMAs, Wh region is reused as fp32 staging (2 waves of 4 warps).
// ---------------------------------------------------------------------------
__global__ __launch_bounds__(256) void gemm_wmma_kernel(
    const float* __restrict__ A, const float* __restrict__ W)
{
    extern __shared__ char smem[];
    __half* Wh = (__half*)smem;              // [g*128 + f], 32 KB
    __half* As = (__half*)(smem + 32768);    // [r*128 + f], 32 KB

    const int tid  = threadIdx.x;
    const int w    = tid >> 5;
    const int lane = tid & 31;
    const int row0 = blockIdx.x * 128;

    // --- load W fp32 -> fp16 smem ---
#pragma unroll
    for (int i = tid; i < FDIM * FDIM / 4; i += 256) {
        float4 v = ((const float4*)W)[i];
        __half2 h0 = __floats2half2_rn(v.x, v.y);
        __half2 h1 = __floats2half2_rn(v.z, v.w);
        uint2 o;
        o.x = *reinterpret_cast<unsigned*>(&h0);
        o.y = *reinterpret_cast<unsigned*>(&h1);
        ((uint2*)Wh)[i] = o;
    }

    // --- load A tile fp32 -> fp16 smem, write A half of g_ABh ---
#pragma unroll
    for (int i = tid; i < 128 * FDIM / 4; i += 256) {
        int r = i >> 5, c4 = i & 31;
        int grow = row0 + r;
        uint2 o;
        if (grow < N_ATOMS) {
            float4 v = ((const float4*)A)[(size_t)grow * (FDIM / 4) + c4];
            __half2 h0 = __floats2half2_rn(v.x, v.y);
            __half2 h1 = __floats2half2_rn(v.z, v.w);
            o.x = *reinterpret_cast<unsigned*>(&h0);
            o.y = *reinterpret_cast<unsigned*>(&h1);
            ((uint2*)g_ABh)[(size_t)grow * 64 + c4 * 2] = o;   // A slot
        } else {
            o.x = 0u; o.y = 0u;
        }
        ((uint2*)As)[i] = o;
    }
    __syncthreads();

    // --- wmma: each warp does 16 rows x 128 cols ---
    wmma::fragment<wmma::accumulator, 16, 16, 16, float> c[8];
#pragma unroll
    for (int n = 0; n < 8; n++) wmma::fill_fragment(c[n], 0.0f);

    const int m0 = w * 16;
#pragma unroll
    for (int k0 = 0; k0 < 8; k0++) {
        wmma::fragment<wmma::matrix_a, 16, 16, 16, __half, wmma::row_major> a;
        wmma::load_matrix_sync(a, As + m0 * FDIM + k0 * 16, FDIM);
#pragma unroll
        for (int n = 0; n < 8; n++) {
            wmma::fragment<wmma::matrix_b, 16, 16, 16, __half, wmma::col_major> bfr;
            // B(k,n) = Wh[n*128 + k]  (W row-major [g][f] == col-major K x N)
            wmma::load_matrix_sync(bfr, Wh + (n * 16) * FDIM + k0 * 16, FDIM);
            wmma::mma_sync(c[n], a, bfr, c[n]);
        }
    }
    __syncthreads();   // MMAs done; Wh region free for staging

    float* stage = (float*)Wh;   // 4 warps x 16x128 fp32 = 32 KB per wave

    // --- stage fp32 -> fp16 -> B half of g_ABh, two waves of 4 warps ---
#pragma unroll
    for (int wave = 0; wave < 2; wave++) {
        if ((w >> 2) == wave) {
            float* sp = stage + (w & 3) * 16 * FDIM;
#pragma unroll
            for (int n = 0; n < 8; n++)
                wmma::store_matrix_sync(sp + n * 16, c[n], FDIM, wmma::mem_row_major);
#pragma unroll
            for (int i = lane; i < 16 * 32; i += 32) {
                int r = i >> 5, c4 = i & 31;
                int grow = row0 + m0 + r;
                if (grow < N_ATOMS) {
                    float4 v = *(const float4*)(sp + r * FDIM + c4 * 4);
                    __half2 h0 = __floats2half2_rn(v.x, v.y);
                    __half2 h1 = __floats2half2_rn(v.z, v.w);
                    uint2 o;
                    o.x = *reinterpret_cast<unsigned*>(&h0);
                    o.y = *reinterpret_cast<unsigned*>(&h1);
                    ((uint2*)g_ABh)[(size_t)grow * 64 + c4 * 2 + 1] = o;  // B slot
                }
            }
        }
        __syncthreads();
    }
}

// ---------------------------------------------------------------------------
// Kernel 2: scatter payload into fixed-stride buckets (4 pairs/thread).
// Payload float4 = { j (bits), f (fp32), (f*ux,f*uy) fp16x2, (f*uz,0) fp16x2 }
// ---------------------------------------------------------------------------
__global__ __launch_bounds__(256) void scatter_kernel(
    const int* __restrict__ idx_i, const int* __restrict__ idx_j,
    const float* __restrict__ fcut, const float* __restrict__ r_ij)
{
    int t = blockIdx.x * blockDim.x + threadIdx.x;
    if (t >= N_PAIRS / 4) return;

    int4   ii = ((const int4*)idx_i)[t];
    int4   jj = ((const int4*)idx_j)[t];
    float4 ff = ((const float4*)fcut)[t];
    float4 r0 = ((const float4*)r_ij)[3 * t + 0];
    float4 r1 = ((const float4*)r_ij)[3 * t + 1];
    float4 r2 = ((const float4*)r_ij)[3 * t + 2];

    float rx[4] = {r0.x, r0.w, r1.z, r2.y};
    float ry[4] = {r0.y, r1.x, r1.w, r2.z};
    float rz[4] = {r0.z, r1.y, r2.x, r2.w};
    int   iv[4] = {ii.x, ii.y, ii.z, ii.w};
    int   jv[4] = {jj.x, jj.y, jj.z, jj.w};
    float fv[4] = {ff.x, ff.y, ff.z, ff.w};

#pragma unroll
    for (int q = 0; q < 4; q++) {
        float finv = fv[q] * rsqrtf(rx[q] * rx[q] + ry[q] * ry[q] + rz[q] * rz[q]);
        __half2 uxy = __floats2half2_rn(rx[q] * finv, ry[q] * finv);
        __half2 uzp = __floats2half2_rn(rz[q] * finv, 0.0f);
        int pos = atomicAdd(&g_cursor[iv[q]], 1);
        if (pos < CAP) {
            float4 pl;
            pl.x = __int_as_float(jv[q]);
            pl.y = fv[q];
            pl.z = *reinterpret_cast<float*>(&uxy);
            pl.w = *reinterpret_cast<float*>(&uzp);
            g_P[(size_t)iv[q] * CAP + pos] = pl;
        }
    }
}

// ---------------------------------------------------------------------------
// Kernel 3: one warp per atom; single LDG.128 gather per pair; pure-FMA loop.
// ---------------------------------------------------------------------------
__device__ __forceinline__ void acc_pair(
    const float4& pl, int lane,
    float rad[4], float sx[4], float sy[4], float sz[4])
{
    int   j = __float_as_int(pl.x);
    float f = pl.y;
    float2 fuxy = __half22float2(*reinterpret_cast<const __half2*>(&pl.z));
    float  fuz  = __low2float(*reinterpret_cast<const __half2*>(&pl.w));

    uint4 uab = *(const uint4*)(g_ABh + (size_t)j * 256 + lane * 8);
    float2 af0 = __half22float2(*reinterpret_cast<__half2*>(&uab.x));
    float2 af1 = __half22float2(*reinterpret_cast<__half2*>(&uab.y));
    float2 bf0 = __half22float2(*reinterpret_cast<__half2*>(&uab.z));
    float2 bf1 = __half22float2(*reinterpret_cast<__half2*>(&uab.w));
    float av[4] = {af0.x, af0.y, af1.x, af1.y};
    float bv[4] = {bf0.x, bf0.y, bf1.x, bf1.y};
#pragma unroll
    for (int k = 0; k < 4; k++) {
        rad[k] += f      * av[k];
        sx[k]  += fuxy.x * bv[k];
        sy[k]  += fuxy.y * bv[k];
        sz[k]  += fuz    * bv[k];
    }
}

__global__ __launch_bounds__(256) void phase2_kernel(
    const float* __restrict__ bvec, float* __restrict__ out)
{
    int atom = (blockIdx.x * blockDim.x + threadIdx.x) >> 5;
    int lane = threadIdx.x & 31;
    if (atom >= N_ATOMS) return;

    const int ntrue = g_cursor[atom];
    const int n     = (ntrue < CAP) ? ntrue : CAP;
    const float4* __restrict__ seg = g_P + (size_t)atom * CAP;
    const int col = lane * 4;

    float rad[4] = {0.f, 0.f, 0.f, 0.f};
    float sx[4]  = {0.f, 0.f, 0.f, 0.f};
    float sy[4]  = {0.f, 0.f, 0.f, 0.f};
    float sz[4]  = {0.f, 0.f, 0.f, 0.f};

    int t = 0;
    for (; t + 4 <= n; t += 4) {
        float4 p0 = seg[t + 0];
        float4 p1 = seg[t + 1];
        float4 p2 = seg[t + 2];
        float4 p3 = seg[t + 3];
        acc_pair(p0, lane, rad, sx, sy, sz);
        acc_pair(p1, lane, rad, sx, sy, sz);
        acc_pair(p2, lane, rad, sx, sy, sz);
        acc_pair(p3, lane, rad, sx, sy, sz);
    }
    for (; t < n; t++) {
        float4 p0 = seg[t];
        acc_pair(p0, lane, rad, sx, sy, sz);
    }

    float4 bq = *(const float4*)(bvec + col);
    float bvv[4] = {bq.x, bq.y, bq.z, bq.w};
    float fn = (float)ntrue;
    float nrm[4];
#pragma unroll
    for (int k = 0; k < 4; k++) {
        float vx = sx[k] + fn * bvv[k];
        float vy = sy[k] + fn * bvv[k];
        float vz = sz[k] + fn * bvv[k];
        nrm[k] = sqrtf(vx * vx + vy * vy + vz * vz + 1e-12f);
    }

    float4 o0 = {nrm[0], nrm[1], nrm[2], nrm[3]};
    float4 o1 = {rad[0], rad[1], rad[2], rad[3]};
    *(float4*)(out + (size_t)atom * (2 * FDIM) + col)        = o0;
    *(float4*)(out + (size_t)atom * (2 * FDIM) + FDIM + col) = o1;
}

// ---------------------------------------------------------------------------
extern "C" void kernel_launch(void* const* d_in, const int* in_sizes, int n_in,
                              void* d_out, int out_size)
{
    const float* A    = (const float*)d_in[0];   // [20000,128]
    const int*   pl   = (const int*)  d_in[1];   // [2,320000]
    const float* fcut = (const float*)d_in[2];   // [320000,1]
    const float* rij  = (const float*)d_in[3];   // [320000,3]
    const float* W    = (const float*)d_in[4];   // [128,128]
    const float* b    = (const float*)d_in[5];   // [128]
    const int* idx_i = pl;
    const int* idx_j = pl + N_PAIRS;
    float* out = (float*)d_out;

    static cudaStream_t s1 = nullptr;
    static cudaEvent_t  ev0 = nullptr, ev1 = nullptr;
    if (!s1) {
        cudaStreamCreateWithFlags(&s1, cudaStreamNonBlocking);
        cudaEventCreateWithFlags(&ev0, cudaEventDisableTiming);
        cudaEventCreateWithFlags(&ev1, cudaEventDisableTiming);
        cudaFuncSetAttribute(gemm_wmma_kernel,
                             cudaFuncAttributeMaxDynamicSharedMemorySize, 65536);
    }

    void* p_cursor;
    cudaGetSymbolAddress(&p_cursor, g_cursor);

    // Fork: GEMM (A,W only) runs concurrently with memset+scatter (pairs only).
    cudaEventRecord(ev0, 0);
    cudaStreamWaitEvent(s1, ev0, 0);
    gemm_wmma_kernel<<<(N_ATOMS + 127) / 128, 256, 65536, s1>>>(A, W);
    cudaEventRecord(ev1, s1);

    cudaMemsetAsync(p_cursor, 0, N_ATOMS * sizeof(int));
    scatter_kernel<<<(N_PAIRS / 4 + 255) / 256, 256>>>(idx_i, idx_j, fcut, rij);

    cudaStreamWaitEvent(0, ev1, 0);   // join before phase2
    phase2_kernel<<<(N_ATOMS * 32 + 255) / 256, 256>>>(b, out);
}